// round 12
// baseline (speedup 1.0000x reference)
#include <cuda_runtime.h>
#include <cuda_fp16.h>
#include <cstdint>

#define SEQ   20
#define BATCH 16384
#define INP   2
#define HID   256
#define EMB   64
#define TLEN  30
#define NG    1024          /* 4*HID */
#define KC    64
#define NSTEP (SEQ + TLEN)
#define NTILE 1024          /* 128 m-blocks x 8 n-blocks per step */

#define M_CTA  128
#define N_CTA  128
#define NSTAGE 3
#define A_TILE 16384        /* 64 k-rows x 128 m-cols x 2B (row pitch 256B) */
#define B_TILE 16384        /* 128 n-rows x 64 k x 2B (row pitch 128B) */
#define STAGE_BYTES (A_TILE + B_TILE)         /* 32KB */
#define SMEM_DYN_TOTAL (NSTAGE * STAGE_BYTES) /* 96KB */

/* MODE: 0 = encoder (NCH 5: chunk0 = x, chunks 1..4 = h),
         1 = encoder t=0, h=0 (NCH 1: x only),
         2 = decoder (NCH 4 h chunks), x + out-projection fused in epilogue */

// ---------------- device scratch (all state [feature][batch]) ----------------
__device__ __half g_W_enc[NG * 320];   // [n][320] = Wh[256] | Wx[64]
__device__ __half g_W_dec[NG * 256];   // [n][256]
__device__ float g_Wxd[NG * 2];
__device__ float g_bias_enc[NG];
__device__ float g_bias_dec[NG];
__device__ __half g_H[2][HID * BATCH];
__device__ float g_c[HID * BATCH];
__device__ __half g_Xe[SEQ * EMB * BATCH];
__device__ int   g_flags[NSTEP][BATCH / M_CTA];

// ---------------- helpers ----------------
__device__ __forceinline__ uint32_t smem_to_u32(const void* p) {
    uint32_t a;
    asm("{ .reg .u64 t; cvta.to.shared.u64 t, %1; cvt.u32.u64 %0, t; }"
        : "=r"(a) : "l"(p));
    return a;
}
#define SWZ(o) ((o) ^ (((o) >> 3) & 0x70))
#define SWZA(kr, c16) ((kr) * 256 + (((c16) ^ ((kr) & 7)) << 4))

#define CP_ASYNC16(s, g) \
    asm volatile("cp.async.cg.shared.global [%0], [%1], 16;" \
                 :: "r"((uint32_t)(s)), "l"(g) : "memory")
#define CP_COMMIT() asm volatile("cp.async.commit_group;" ::: "memory")
template <int N>
__device__ __forceinline__ void cp_wait() {
    asm volatile("cp.async.wait_group %0;" :: "n"(N) : "memory");
}

__device__ __forceinline__ void wait_flag(int s, int mb) {
    if (threadIdx.x == 0) {
        volatile int* f = &g_flags[s][mb];
        while (*f != 8) { __nanosleep(32); }
        __threadfence();
    }
    __syncthreads();
}
__device__ __forceinline__ void signal_flag(int s, int mb) {
    __syncthreads();
    if (threadIdx.x == 0) {
        __threadfence();
        atomicAdd(&g_flags[s][mb], 1);
    }
}

__device__ __forceinline__ void ldm_x4(uint32_t* r, uint32_t a) {
    asm volatile("ldmatrix.sync.aligned.m8n8.x4.shared.b16 {%0,%1,%2,%3}, [%4];"
                 : "=r"(r[0]), "=r"(r[1]), "=r"(r[2]), "=r"(r[3]) : "r"(a));
}
__device__ __forceinline__ void ldm_x4_trans(uint32_t* r, uint32_t a) {
    asm volatile("ldmatrix.sync.aligned.m8n8.x4.trans.shared.b16 {%0,%1,%2,%3}, [%4];"
                 : "=r"(r[0]), "=r"(r[1]), "=r"(r[2]), "=r"(r[3]) : "r"(a));
}
__device__ __forceinline__ void mma_f16(float* c, const uint32_t* a,
                                        uint32_t b0, uint32_t b1) {
    asm volatile(
        "mma.sync.aligned.m16n8k16.row.col.f32.f16.f16.f32 "
        "{%0,%1,%2,%3}, {%4,%5,%6,%7}, {%8,%9}, {%0,%1,%2,%3};"
        : "+f"(c[0]), "+f"(c[1]), "+f"(c[2]), "+f"(c[3])
        : "r"(a[0]), "r"(a[1]), "r"(a[2]), "r"(a[3]), "r"(b0), "r"(b1));
}

__device__ __forceinline__ float fsigmoid(float x) { return 1.0f / (1.0f + __expf(-x)); }
__device__ __forceinline__ float ftanh(float x)    { return 2.0f / (1.0f + __expf(-2.0f * x)) - 1.0f; }

// ---------------- prep kernels ----------------
__global__ void pack_enc_kernel(const float* __restrict__ W_ih,
                                const float* __restrict__ W_hh,
                                const float* __restrict__ b) {
    int idx = blockIdx.x * blockDim.x + threadIdx.x;
    if (idx < NG * 320) {
        int n = idx / 320, kk = idx % 320;
        int j = n >> 2, g = n & 3;
        int row = g * HID + j;
        float v = (kk < 256) ? W_hh[row * HID + kk] : W_ih[row * EMB + (kk - 256)];
        g_W_enc[idx] = __float2half_rn(v);
    }
    if (idx < NG) {
        int j = idx >> 2, g = idx & 3;
        g_bias_enc[idx] = b[g * HID + j];
    }
}

__global__ void pack_dec_kernel(const float* __restrict__ W_ih,
                                const float* __restrict__ W_hh,
                                const float* __restrict__ b) {
    int idx = blockIdx.x * blockDim.x + threadIdx.x;
    if (idx < NG * 256) {
        int n = idx / 256, kk = idx % 256;
        int j = n >> 2, g = n & 3;
        g_W_dec[idx] = __float2half_rn(W_hh[(g * HID + j) * HID + kk]);
    }
    if (idx < NG) {
        int j = idx >> 2, g = idx & 3;
        g_bias_dec[idx] = b[g * HID + j];
    }
    if (idx < NG * 2) {
        int n = idx >> 1, k = idx & 1;
        int j = n >> 2, g = n & 3;
        g_Wxd[idx] = W_ih[(g * HID + j) * INP + k];
    }
}

__global__ void init_state_kernel() {
    int idx = blockIdx.x * blockDim.x + threadIdx.x;
    if (idx < HID * BATCH) {
        g_H[0][idx] = __float2half(0.0f);
        g_c[idx]    = 0.0f;
    }
    if (idx < NSTEP * (BATCH / M_CTA)) ((int*)g_flags)[idx] = 0;
}

__global__ void init_out_kernel(const float* __restrict__ b_out,
                                float* __restrict__ out) {
    int idx = blockIdx.x * blockDim.x + threadIdx.x;
    if (idx < TLEN * BATCH * 2) out[idx] = b_out[idx & 1];
}

__global__ void embed_kernel(const float* __restrict__ x,
                             const float* __restrict__ W_emb,
                             const float* __restrict__ b_emb) {
    int idx = blockIdx.x * blockDim.x + threadIdx.x;
    if (idx >= SEQ * EMB * BATCH) return;
    int b  = idx & (BATCH - 1);
    int te = idx >> 14;
    int e  = te & (EMB - 1);
    int t  = te >> 6;
    float x0 = x[((size_t)t * BATCH + b) * 2 + 0];
    float x1 = x[((size_t)t * BATCH + b) * 2 + 1];
    float v = b_emb[e] + x0 * W_emb[e * 2 + 0] + x1 * W_emb[e * 2 + 1];
    g_Xe[idx] = __float2half_rn(v);
}

// ---------------- one (step, tile) unit: GEMM + fused cell update ----------------
template <int MODE>
__device__ __forceinline__ void run_unit(
    char* smem_raw, uint32_t sb, int s, int mb, int n0,
    const float* __restrict__ x, float* __restrict__ out,
    const float* __restrict__ Wout) {
    constexpr int NCH = (MODE == 0) ? 5 : (MODE == 1 ? 1 : 4);
    constexpr int WS  = (MODE == 2) ? 256 : 320;
    const int tid  = threadIdx.x;
    const int warp = tid >> 5, lane = tid & 31;
    const int wm = warp >> 2, wn = warp & 3;
    const int m0 = mb * M_CTA;
    const int ppi = s & 1;
    const int t = s;                         // encoder timestep
    const int td = s - SEQ;                  // decoder timestep

    const __half* __restrict__ Wt  = (MODE == 2) ? g_W_dec : g_W_enc;
    const float* __restrict__ bias = (MODE == 2) ? g_bias_dec : g_bias_enc;
    const __half* __restrict__ hh  = g_H[ppi];
    __half* __restrict__ hho       = g_H[ppi ^ 1];
    const __half* __restrict__ xh  = g_Xe + (size_t)t * EMB * BATCH;
    const float* prev = nullptr;
    float* outp = nullptr;
    if (MODE == 2) {
        prev = (td == 0) ? (x + (size_t)(SEQ - 1) * BATCH * INP)
                         : (out + (size_t)(td - 1) * BATCH * 2);
        outp = out + (size_t)td * BATCH * 2;
    }

    auto a_src = [&](int ck) -> const __half* {
        if (MODE == 0) return (ck == 0) ? xh : hh + (size_t)((ck - 1) * KC) * BATCH;
        if (MODE == 1) return xh;
        return hh + (size_t)(ck * KC) * BATCH;
    };
    auto w_off = [&](int ck) -> int {
        if (MODE == 0) return (ck == 0) ? 256 : (ck - 1) * KC;
        if (MODE == 1) return 256;
        return ck * KC;
    };
    auto load_W = [&](int ck, int st) {
        const uint32_t sW = sb + st * STAGE_BYTES + A_TILE;
        const int rw = tid >> 1;
        const __half* gw = Wt + (size_t)(n0 + rw) * WS + w_off(ck);
#pragma unroll
        for (int i = 0; i < 4; i++) {
            const int seg = (tid & 1) * 4 + i;
            CP_ASYNC16(sW + SWZ(rw * 128 + seg * 16), gw + seg * 8);
        }
    };
    auto load_A = [&](int ck, int st) {
        const uint32_t sA = sb + st * STAGE_BYTES;
        const int kr = tid >> 2;
        const __half* g = a_src(ck) + (size_t)kr * BATCH + m0;
#pragma unroll
        for (int i = 0; i < 4; i++) {
            const int c16 = (tid & 3) * 4 + i;
            CP_ASYNC16(sA + SWZA(kr, c16), g + c16 * 8);
        }
    };

    float acc[4][4][4];
#pragma unroll
    for (int a = 0; a < 4; a++)
#pragma unroll
        for (int b = 0; b < 4; b++)
#pragma unroll
            for (int c = 0; c < 4; c++) acc[a][b][c] = 0.0f;

    // ---- prologue: flag-independent loads first, wait producers, then A ----
    if (MODE == 0) {
        load_W(0, 0); load_A(0, 0); CP_COMMIT();
        load_W(1, 1);
        wait_flag(s - 1, mb);
        load_A(1, 1); CP_COMMIT();
    } else if (MODE == 1) {
        load_W(0, 0); load_A(0, 0); CP_COMMIT();
        CP_COMMIT();
    } else {
        load_W(0, 0); load_W(1, 1);
        wait_flag(s - 1, mb);
        load_A(0, 0); CP_COMMIT();
        load_A(1, 1); CP_COMMIT();
    }

    for (int ck = 0; ck < NCH; ck++) {
        const int st = ck % NSTAGE;
        cp_wait<1>();
        __syncthreads();
        if (ck + 2 < NCH) {
            const int st2 = (ck + 2) % NSTAGE;
            load_W(ck + 2, st2);
            load_A(ck + 2, st2);
        }
        CP_COMMIT();

        const uint32_t sA = sb + st * STAGE_BYTES;
        const uint32_t sW = sA + A_TILE;
#pragma unroll
        for (int k16 = 0; k16 < 4; k16++) {
            uint32_t afr[4][4];
            const int kr = k16 * 16 + (lane & 7) + ((lane & 16) >> 1);
#pragma unroll
            for (int mt = 0; mt < 4; mt++) {
                const int mc = wm * 64 + mt * 16 + (lane & 8);
                ldm_x4_trans(afr[mt], sA + SWZA(kr, mc >> 3));
            }
            uint32_t bfr[2][4];
#pragma unroll
            for (int p = 0; p < 2; p++) {
                const int row  = wn * 32 + p * 16 + (lane & 7) + ((lane & 16) >> 1);
                const int kcol = k16 * 16 + ((lane & 8) ? 8 : 0);
                ldm_x4(bfr[p], sW + SWZ(row * 128 + kcol * 2));
            }
#pragma unroll
            for (int mt = 0; mt < 4; mt++)
#pragma unroll
                for (int nt = 0; nt < 4; nt++)
                    mma_f16(acc[mt][nt], afr[mt],
                            bfr[nt >> 1][(nt & 1) * 2],
                            bfr[nt >> 1][(nt & 1) * 2 + 1]);
        }
    }

    // ---- epilogue ----
    const int odd = lane & 1;
    const int q   = (lane & 2) >> 1;
    float s0m[4] = {0, 0, 0, 0}, s1m[4] = {0, 0, 0, 0};
    float xv0[4], xv1[4];
    if (MODE == 2) {
#pragma unroll
        for (int mt = 0; mt < 4; mt++) {
            const int mrow = m0 + wm * 64 + mt * 16 + (lane >> 2) + 8 * odd;
            xv0[mt] = prev[mrow * 2 + 0];
            xv1[mt] = prev[mrow * 2 + 1];
        }
    }
#pragma unroll
    for (int nt = 0; nt < 4; nt++) {
        const int nb = n0 + wn * 32 + nt * 8 + q * 4;
        const float4 bv = *(const float4*)&bias[nb];
        const int j = nb >> 2;
        float wx0[4], wx1[4], w_o0 = 0.0f, w_o1 = 0.0f;
        if (MODE == 2) {
#pragma unroll
            for (int r = 0; r < 4; r++) {
                wx0[r] = g_Wxd[(nb + r) * 2 + 0];
                wx1[r] = g_Wxd[(nb + r) * 2 + 1];
            }
            w_o0 = Wout[j];
            w_o1 = Wout[HID + j];
        }
#pragma unroll
        for (int mt = 0; mt < 4; mt++) {
            float o0 = __shfl_xor_sync(0xffffffffu, acc[mt][nt][0], 1);
            float o1 = __shfl_xor_sync(0xffffffffu, acc[mt][nt][1], 1);
            float o2 = __shfl_xor_sync(0xffffffffu, acc[mt][nt][2], 1);
            float o3 = __shfl_xor_sync(0xffffffffu, acc[mt][nt][3], 1);
            float gi, gf, gg, go;
            if (!odd) { gi = acc[mt][nt][0]; gf = acc[mt][nt][1]; gg = o0; go = o1; }
            else      { gi = o2; gf = o3; gg = acc[mt][nt][2]; go = acc[mt][nt][3]; }
            const int mrow = m0 + wm * 64 + mt * 16 + (lane >> 2) + 8 * odd;
            if (MODE == 2) {
                gi = fmaf(xv0[mt], wx0[0], fmaf(xv1[mt], wx1[0], gi));
                gf = fmaf(xv0[mt], wx0[1], fmaf(xv1[mt], wx1[1], gf));
                gg = fmaf(xv0[mt], wx0[2], fmaf(xv1[mt], wx1[2], gg));
                go = fmaf(xv0[mt], wx0[3], fmaf(xv1[mt], wx1[3], go));
            }
            gi += bv.x; gf += bv.y; gg += bv.z; go += bv.w;
            const size_t sidx = (size_t)j * BATCH + mrow;
            float cold = (MODE == 1) ? 0.0f : g_c[sidx];
            float cn = fsigmoid(gf) * cold + fsigmoid(gi) * ftanh(gg);
            g_c[sidx] = cn;
            float hn = fsigmoid(go) * ftanh(cn);
            hho[sidx] = __float2half_rn(hn);
            if (MODE == 2) {
                s0m[mt] = fmaf(hn, w_o0, s0m[mt]);
                s1m[mt] = fmaf(hn, w_o1, s1m[mt]);
            }
        }
    }

    if (MODE == 2) {
        float* sOut = (float*)smem_raw;   // 128 rows x 2 floats (stage-0 area)
        __syncthreads();                  // GEMM smem reads done
        sOut[tid] = 0.0f;
        __syncthreads();
#pragma unroll
        for (int mt = 0; mt < 4; mt++) {
            s0m[mt] += __shfl_xor_sync(0xffffffffu, s0m[mt], 2);
            s1m[mt] += __shfl_xor_sync(0xffffffffu, s1m[mt], 2);
        }
        if (!(lane & 2)) {
#pragma unroll
            for (int mt = 0; mt < 4; mt++) {
                const int r = wm * 64 + mt * 16 + (lane >> 2) + 8 * odd;
                atomicAdd(&sOut[r * 2 + 0], s0m[mt]);
                atomicAdd(&sOut[r * 2 + 1], s1m[mt]);
            }
        }
        __syncthreads();
        atomicAdd(&outp[(size_t)(m0 + (tid >> 1)) * 2 + (tid & 1)], sOut[tid]);
    }

    // publish (also orders smem reuse for this CTA's next unit)
    signal_flag(s, mb);
}

// ---------------- persistent kernel: all steps, all tiles ----------------
__global__ void __launch_bounds__(256, 2)
lstm_persistent_kernel(const float* __restrict__ x,
                       float* __restrict__ out,
                       const float* __restrict__ Wout) {
    extern __shared__ __align__(1024) char smem_raw[];
    const uint32_t sb = smem_to_u32(smem_raw);
    const int ncta = gridDim.x;
    const int total = NSTEP * NTILE;

    for (int g = blockIdx.x; g < total; g += ncta) {
        const int s    = g >> 10;
        const int tile = g & (NTILE - 1);
        const int mb   = tile >> 3;       // n fast within m-block
        const int n0   = (tile & 7) * N_CTA;
        if (s == 0)           run_unit<1>(smem_raw, sb, s, mb, n0, x, out, Wout);
        else if (s < SEQ)     run_unit<0>(smem_raw, sb, s, mb, n0, x, out, Wout);
        else                  run_unit<2>(smem_raw, sb, s, mb, n0, x, out, Wout);
    }
}

// ---------------- launch ----------------
extern "C" void kernel_launch(void* const* d_in, const int* in_sizes, int n_in,
                              void* d_out, int out_size) {
    const float* x        = (const float*)d_in[0];
    const float* W_emb    = (const float*)d_in[1];
    const float* b_emb    = (const float*)d_in[2];
    const float* W_ih_enc = (const float*)d_in[3];
    const float* W_hh_enc = (const float*)d_in[4];
    const float* b_enc    = (const float*)d_in[5];
    const float* W_ih_dec = (const float*)d_in[6];
    const float* W_hh_dec = (const float*)d_in[7];
    const float* b_dec    = (const float*)d_in[8];
    const float* W_out    = (const float*)d_in[9];
    const float* b_out    = (const float*)d_in[10];
    float* out = (float*)d_out;

    cudaFuncSetAttribute(lstm_persistent_kernel,
                         cudaFuncAttributeMaxDynamicSharedMemorySize, SMEM_DYN_TOTAL);

    int nsm = 148;
    cudaDeviceGetAttribute(&nsm, cudaDevAttrMultiProcessorCount, 0);
    const int ncta = nsm * 2;   // matches __launch_bounds__(256,2) residency

    pack_enc_kernel<<<(NG * 320 + 255) / 256, 256>>>(W_ih_enc, W_hh_enc, b_enc);
    pack_dec_kernel<<<(NG * 256 + 255) / 256, 256>>>(W_ih_dec, W_hh_dec, b_dec);
    init_state_kernel<<<(HID * BATCH + 255) / 256, 256>>>();
    init_out_kernel<<<(TLEN * BATCH * 2 + 255) / 256, 256>>>(b_out, out);
    embed_kernel<<<(SEQ * EMB * BATCH + 255) / 256, 256>>>(x, W_emb, b_emb);

    lstm_persistent_kernel<<<ncta, 256, SMEM_DYN_TOTAL>>>(x, out, W_out);
}

// round 13
// speedup vs baseline: 1.0946x; 1.0946x over previous
#include <cuda_runtime.h>
#include <cuda_fp16.h>
#include <cstdint>

#define SEQ   20
#define BATCH 16384
#define INP   2
#define HID   256
#define EMB   64
#define TLEN  30
#define NG    1024          /* 4*HID */
#define KC    64

#define M_CTA  128
#define N_CTA  128
#define NSTAGE 3
#define A_TILE 16384        /* 64 k-rows x 128 m-cols x 2B (row pitch 256B) */
#define B_TILE 16384        /* 128 n-rows x 64 k x 2B (row pitch 128B) */
#define STAGE_BYTES (A_TILE + B_TILE)         /* 32KB */
#define SMEM_DYN_TOTAL (NSTAGE * STAGE_BYTES) /* 96KB */

/* MODE: 0 = encoder (NCH 5: chunk0 = x, chunks 1..4 = h),
         1 = encoder t=0, h=0 (NCH 1: x only),
         2 = decoder (NCH 4 h chunks), x + out-projection fused in epilogue */

// ---------------- device scratch (all state [feature][batch]) ----------------
__device__ __half g_W_enc[NG * 320];   // [n][320] = Wh[256] | Wx[64]
__device__ __half g_W_dec[NG * 256];   // [n][256]
__device__ float g_Wxd[NG * 2];        // decoder W_ih [n][2] fp32
__device__ float g_bias_enc[NG];
__device__ float g_bias_dec[NG];
__device__ __half g_H[2][HID * BATCH]; // [j][b] single fp16 plane
__device__ float g_c[HID * BATCH];     // [j][b]
__device__ __half g_Xe[SEQ * EMB * BATCH];

// ---------------- helpers ----------------
__device__ __forceinline__ uint32_t smem_to_u32(const void* p) {
    uint32_t a;
    asm("{ .reg .u64 t; cvta.to.shared.u64 t, %1; cvt.u32.u64 %0, t; }"
        : "=r"(a) : "l"(p));
    return a;
}
#define SWZ(o) ((o) ^ (((o) >> 3) & 0x70))
#define SWZA(kr, c16) ((kr) * 256 + (((c16) ^ ((kr) & 7)) << 4))

#define CP_ASYNC16(s, g) \
    asm volatile("cp.async.cg.shared.global [%0], [%1], 16;" \
                 :: "r"((uint32_t)(s)), "l"(g) : "memory")
#define CP_COMMIT() asm volatile("cp.async.commit_group;" ::: "memory")
template <int N>
__device__ __forceinline__ void cp_wait() {
    asm volatile("cp.async.wait_group %0;" :: "n"(N) : "memory");
}

#define PDL_WAIT()    asm volatile("griddepcontrol.wait;" ::: "memory")
#define PDL_TRIGGER() asm volatile("griddepcontrol.launch_dependents;" ::: "memory")

__device__ __forceinline__ void ldm_x4(uint32_t* r, uint32_t a) {
    asm volatile("ldmatrix.sync.aligned.m8n8.x4.shared.b16 {%0,%1,%2,%3}, [%4];"
                 : "=r"(r[0]), "=r"(r[1]), "=r"(r[2]), "=r"(r[3]) : "r"(a));
}
__device__ __forceinline__ void ldm_x4_trans(uint32_t* r, uint32_t a) {
    asm volatile("ldmatrix.sync.aligned.m8n8.x4.trans.shared.b16 {%0,%1,%2,%3}, [%4];"
                 : "=r"(r[0]), "=r"(r[1]), "=r"(r[2]), "=r"(r[3]) : "r"(a));
}
__device__ __forceinline__ void mma_f16(float* c, const uint32_t* a,
                                        uint32_t b0, uint32_t b1) {
    asm volatile(
        "mma.sync.aligned.m16n8k16.row.col.f32.f16.f16.f32 "
        "{%0,%1,%2,%3}, {%4,%5,%6,%7}, {%8,%9}, {%0,%1,%2,%3};"
        : "+f"(c[0]), "+f"(c[1]), "+f"(c[2]), "+f"(c[3])
        : "r"(a[0]), "r"(a[1]), "r"(a[2]), "r"(a[3]), "r"(b0), "r"(b1));
}

__device__ __forceinline__ float fsigmoid(float x) { return 1.0f / (1.0f + __expf(-x)); }
__device__ __forceinline__ float ftanh(float x) {
    float y;
    asm("tanh.approx.f32 %0, %1;" : "=f"(y) : "f"(x));
    return y;
}

// ---------------- prep kernels ----------------
__global__ void pack_enc_kernel(const float* __restrict__ W_ih,
                                const float* __restrict__ W_hh,
                                const float* __restrict__ b) {
    int idx = blockIdx.x * blockDim.x + threadIdx.x;
    if (idx < NG * 320) {
        int n = idx / 320, kk = idx % 320;
        int j = n >> 2, g = n & 3;
        int row = g * HID + j;
        float v = (kk < 256) ? W_hh[row * HID + kk] : W_ih[row * EMB + (kk - 256)];
        g_W_enc[idx] = __float2half_rn(v);
    }
    if (idx < NG) {
        int j = idx >> 2, g = idx & 3;
        g_bias_enc[idx] = b[g * HID + j];
    }
}

__global__ void pack_dec_kernel(const float* __restrict__ W_ih,
                                const float* __restrict__ W_hh,
                                const float* __restrict__ b) {
    int idx = blockIdx.x * blockDim.x + threadIdx.x;
    if (idx < NG * 256) {
        int n = idx / 256, kk = idx % 256;
        int j = n >> 2, g = n & 3;
        g_W_dec[idx] = __float2half_rn(W_hh[(g * HID + j) * HID + kk]);
    }
    if (idx < NG) {
        int j = idx >> 2, g = idx & 3;
        g_bias_dec[idx] = b[g * HID + j];
    }
    if (idx < NG * 2) {
        int n = idx >> 1, k = idx & 1;
        int j = n >> 2, g = n & 3;
        g_Wxd[idx] = W_ih[(g * HID + j) * INP + k];
    }
}

// merged: h/c zero-init + out bias-init
__global__ void init_all_kernel(const float* __restrict__ b_out,
                                float* __restrict__ out) {
    int idx = blockIdx.x * blockDim.x + threadIdx.x;
    if (idx < HID * BATCH) {
        g_H[0][idx] = __float2half(0.0f);
        g_c[idx]    = 0.0f;
    }
    if (idx < TLEN * BATCH * 2) out[idx] = b_out[idx & 1];
}

__global__ void embed_kernel(const float* __restrict__ x,
                             const float* __restrict__ W_emb,
                             const float* __restrict__ b_emb) {
    int idx = blockIdx.x * blockDim.x + threadIdx.x;
    if (idx >= SEQ * EMB * BATCH) return;
    int b  = idx & (BATCH - 1);
    int te = idx >> 14;
    int e  = te & (EMB - 1);
    int t  = te >> 6;
    float x0 = x[((size_t)t * BATCH + b) * 2 + 0];
    float x1 = x[((size_t)t * BATCH + b) * 2 + 1];
    float v = b_emb[e] + x0 * W_emb[e * 2 + 0] + x1 * W_emb[e * 2 + 1];
    g_Xe[idx] = __float2half_rn(v);
}

// ---------------- fused HMMA LSTM step ----------------
// CTA 128(M batch)x128(N gates), 256 thr, 8 warps (2m x 4n), warp 64x32.
template <int MODE>
__global__ void __launch_bounds__(256, 2)
lstm_step_kernel(int t, int ppi,
                 const float* __restrict__ prev,   // MODE 2: [b][2] fp32
                 float* __restrict__ outp,         // MODE 2: out[t] [b][2]
                 const float* __restrict__ Wout) { // MODE 2: [2][256]
    constexpr int NCH = (MODE == 0) ? 5 : (MODE == 1 ? 1 : 4);
    constexpr int WS  = (MODE == 2) ? 256 : 320;
    extern __shared__ __align__(1024) char smem_raw[];
    const uint32_t sb = smem_to_u32(smem_raw);
    const int tid  = threadIdx.x;
    const int warp = tid >> 5, lane = tid & 31;
    const int wm = warp >> 2, wn = warp & 3;
    const int m0 = blockIdx.x * M_CTA, n0 = blockIdx.y * N_CTA;

    const __half* __restrict__ Wt  = (MODE == 2) ? g_W_dec : g_W_enc;
    const float* __restrict__ bias = (MODE == 2) ? g_bias_dec : g_bias_enc;
    const __half* __restrict__ hh  = g_H[ppi];
    __half* __restrict__ hho       = g_H[ppi ^ 1];
    const __half* __restrict__ xh  = g_Xe + (size_t)t * EMB * BATCH;

    auto a_src = [&](int ck) -> const __half* {
        if (MODE == 0) return (ck == 0) ? xh : hh + (size_t)((ck - 1) * KC) * BATCH;
        if (MODE == 1) return xh;
        return hh + (size_t)(ck * KC) * BATCH;
    };
    auto w_off = [&](int ck) -> int {
        if (MODE == 0) return (ck == 0) ? 256 : (ck - 1) * KC;
        if (MODE == 1) return 256;
        return ck * KC;
    };

    auto load_W = [&](int ck, int st) {
        const uint32_t sW = sb + st * STAGE_BYTES + A_TILE;
        const int rw = tid >> 1;
        const __half* gw = Wt + (size_t)(n0 + rw) * WS + w_off(ck);
#pragma unroll
        for (int i = 0; i < 4; i++) {
            const int seg = (tid & 1) * 4 + i;
            CP_ASYNC16(sW + SWZ(rw * 128 + seg * 16), gw + seg * 8);
        }
    };
    auto load_A = [&](int ck, int st) {
        const uint32_t sA = sb + st * STAGE_BYTES;
        const int kr = tid >> 2;
        const __half* g = a_src(ck) + (size_t)kr * BATCH + m0;
#pragma unroll
        for (int i = 0; i < 4; i++) {
            const int c16 = (tid & 3) * 4 + i;
            CP_ASYNC16(sA + SWZA(kr, c16), g + c16 * 8);
        }
    };

    float acc[4][4][4];
#pragma unroll
    for (int a = 0; a < 4; a++)
#pragma unroll
        for (int b = 0; b < 4; b++)
#pragma unroll
            for (int c = 0; c < 4; c++) acc[a][b][c] = 0.0f;

    // ---- prologue: PDL-independent loads first, wait, then h-dependent A ----
    if (MODE == 0) {
        load_W(0, 0); load_A(0, 0); CP_COMMIT();   // x chunk: fully independent
        load_W(1, 1);
        PDL_WAIT();
        load_A(1, 1); CP_COMMIT();
    } else if (MODE == 1) {
        load_W(0, 0); load_A(0, 0); CP_COMMIT();
        CP_COMMIT();    // uniform 2 groups
    } else {
        load_W(0, 0); load_W(1, 1);
        PDL_WAIT();
        load_A(0, 0); CP_COMMIT();
        load_A(1, 1); CP_COMMIT();
    }

    for (int ck = 0; ck < NCH; ck++) {
        const int st = ck % NSTAGE;
        cp_wait<1>();
        __syncthreads();
        if (ck + 2 < NCH) {
            const int st2 = (ck + 2) % NSTAGE;
            load_W(ck + 2, st2);
            load_A(ck + 2, st2);
        }
        CP_COMMIT();
        // all loads for this step issued: release the dependent grid early
        if (ck == NCH - 1) PDL_TRIGGER();

        const uint32_t sA = sb + st * STAGE_BYTES;
        const uint32_t sW = sA + A_TILE;
#pragma unroll
        for (int k16 = 0; k16 < 4; k16++) {
            uint32_t afr[4][4];
            const int kr = k16 * 16 + (lane & 7) + ((lane & 16) >> 1);
#pragma unroll
            for (int mt = 0; mt < 4; mt++) {
                const int mc = wm * 64 + mt * 16 + (lane & 8);
                ldm_x4_trans(afr[mt], sA + SWZA(kr, mc >> 3));
            }
            uint32_t bfr[2][4];
#pragma unroll
            for (int p = 0; p < 2; p++) {
                const int row  = wn * 32 + p * 16 + (lane & 7) + ((lane & 16) >> 1);
                const int kcol = k16 * 16 + ((lane & 8) ? 8 : 0);
                ldm_x4(bfr[p], sW + SWZ(row * 128 + kcol * 2));
            }
#pragma unroll
            for (int mt = 0; mt < 4; mt++)
#pragma unroll
                for (int nt = 0; nt < 4; nt++)
                    mma_f16(acc[mt][nt], afr[mt],
                            bfr[nt >> 1][(nt & 1) * 2],
                            bfr[nt >> 1][(nt & 1) * 2 + 1]);
        }
    }

    // ---- epilogue ----
    const int odd = lane & 1;
    const int q   = (lane & 2) >> 1;
    float s0m[4] = {0, 0, 0, 0}, s1m[4] = {0, 0, 0, 0};
    float xv0[4], xv1[4];
    if (MODE == 2) {
#pragma unroll
        for (int mt = 0; mt < 4; mt++) {
            const int mrow = m0 + wm * 64 + mt * 16 + (lane >> 2) + 8 * odd;
            xv0[mt] = prev[mrow * 2 + 0];
            xv1[mt] = prev[mrow * 2 + 1];
        }
    }
#pragma unroll
    for (int nt = 0; nt < 4; nt++) {
        const int nb = n0 + wn * 32 + nt * 8 + q * 4;
        const float4 bv = *(const float4*)&bias[nb];
        const int j = nb >> 2;
        float wx0[4], wx1[4], w_o0 = 0.0f, w_o1 = 0.0f;
        if (MODE == 2) {
#pragma unroll
            for (int r = 0; r < 4; r++) {
                wx0[r] = g_Wxd[(nb + r) * 2 + 0];
                wx1[r] = g_Wxd[(nb + r) * 2 + 1];
            }
            w_o0 = Wout[j];
            w_o1 = Wout[HID + j];
        }
#pragma unroll
        for (int mt = 0; mt < 4; mt++) {
            float o0 = __shfl_xor_sync(0xffffffffu, acc[mt][nt][0], 1);
            float o1 = __shfl_xor_sync(0xffffffffu, acc[mt][nt][1], 1);
            float o2 = __shfl_xor_sync(0xffffffffu, acc[mt][nt][2], 1);
            float o3 = __shfl_xor_sync(0xffffffffu, acc[mt][nt][3], 1);
            float gi, gf, gg, go;
            if (!odd) { gi = acc[mt][nt][0]; gf = acc[mt][nt][1]; gg = o0; go = o1; }
            else      { gi = o2; gf = o3; gg = acc[mt][nt][2]; go = acc[mt][nt][3]; }
            const int mrow = m0 + wm * 64 + mt * 16 + (lane >> 2) + 8 * odd;
            if (MODE == 2) {
                gi = fmaf(xv0[mt], wx0[0], fmaf(xv1[mt], wx1[0], gi));
                gf = fmaf(xv0[mt], wx0[1], fmaf(xv1[mt], wx1[1], gf));
                gg = fmaf(xv0[mt], wx0[2], fmaf(xv1[mt], wx1[2], gg));
                go = fmaf(xv0[mt], wx0[3], fmaf(xv1[mt], wx1[3], go));
            }
            gi += bv.x; gf += bv.y; gg += bv.z; go += bv.w;
            const size_t sidx = (size_t)j * BATCH + mrow;
            float cold = (MODE == 1) ? 0.0f : g_c[sidx];
            float cn = fsigmoid(gf) * cold + fsigmoid(gi) * ftanh(gg);
            g_c[sidx] = cn;
            float hn = fsigmoid(go) * ftanh(cn);
            hho[sidx] = __float2half_rn(hn);
            if (MODE == 2) {
                s0m[mt] = fmaf(hn, w_o0, s0m[mt]);
                s1m[mt] = fmaf(hn, w_o1, s1m[mt]);
            }
        }
    }

    // ---- MODE 2: reduce out partials and accumulate to out[t] ----
    if (MODE == 2) {
        float* sOut = (float*)smem_raw;   // 128 rows x 2
        __syncthreads();                  // all GEMM smem reads done
        sOut[tid] = 0.0f;
        __syncthreads();
#pragma unroll
        for (int mt = 0; mt < 4; mt++) {
            s0m[mt] += __shfl_xor_sync(0xffffffffu, s0m[mt], 2);
            s1m[mt] += __shfl_xor_sync(0xffffffffu, s1m[mt], 2);
        }
        if (!(lane & 2)) {
#pragma unroll
            for (int mt = 0; mt < 4; mt++) {
                const int r = wm * 64 + mt * 16 + (lane >> 2) + 8 * odd;
                atomicAdd(&sOut[r * 2 + 0], s0m[mt]);
                atomicAdd(&sOut[r * 2 + 1], s1m[mt]);
            }
        }
        __syncthreads();
        atomicAdd(&outp[(size_t)(m0 + (tid >> 1)) * 2 + (tid & 1)], sOut[tid]);
    }
}

// ---------------- host-side PDL launch helper ----------------
template <int MODE>
static void launch_step(dim3 grid, bool pdl, int t, int pp,
                        const float* prev, float* outp, const float* Wout) {
    cudaLaunchConfig_t cfg = {};
    cfg.gridDim = grid;
    cfg.blockDim = dim3(256, 1, 1);
    cfg.dynamicSmemBytes = SMEM_DYN_TOTAL;
    cfg.stream = 0;
    cudaLaunchAttribute attr[1];
    if (pdl) {
        attr[0].id = cudaLaunchAttributeProgrammaticStreamSerialization;
        attr[0].val.programmaticStreamSerializationAllowed = 1;
        cfg.attrs = attr;
        cfg.numAttrs = 1;
    }
    cudaLaunchKernelEx(&cfg, lstm_step_kernel<MODE>, t, pp, prev, outp, Wout);
}

// ---------------- launch ----------------
extern "C" void kernel_launch(void* const* d_in, const int* in_sizes, int n_in,
                              void* d_out, int out_size) {
    const float* x        = (const float*)d_in[0];
    const float* W_emb    = (const float*)d_in[1];
    const float* b_emb    = (const float*)d_in[2];
    const float* W_ih_enc = (const float*)d_in[3];
    const float* W_hh_enc = (const float*)d_in[4];
    const float* b_enc    = (const float*)d_in[5];
    const float* W_ih_dec = (const float*)d_in[6];
    const float* W_hh_dec = (const float*)d_in[7];
    const float* b_dec    = (const float*)d_in[8];
    const float* W_out    = (const float*)d_in[9];
    const float* b_out    = (const float*)d_in[10];
    float* out = (float*)d_out;

    cudaFuncSetAttribute(lstm_step_kernel<0>,
                         cudaFuncAttributeMaxDynamicSharedMemorySize, SMEM_DYN_TOTAL);
    cudaFuncSetAttribute(lstm_step_kernel<1>,
                         cudaFuncAttributeMaxDynamicSharedMemorySize, SMEM_DYN_TOTAL);
    cudaFuncSetAttribute(lstm_step_kernel<2>,
                         cudaFuncAttributeMaxDynamicSharedMemorySize, SMEM_DYN_TOTAL);

    pack_enc_kernel<<<(NG * 320 + 255) / 256, 256>>>(W_ih_enc, W_hh_enc, b_enc);
    pack_dec_kernel<<<(NG * 256 + 255) / 256, 256>>>(W_ih_dec, W_hh_dec, b_dec);
    init_all_kernel<<<(HID * BATCH + 255) / 256, 256>>>(b_out, out);
    embed_kernel<<<(SEQ * EMB * BATCH + 255) / 256, 256>>>(x, W_emb, b_emb);

    dim3 grid(BATCH / M_CTA, NG / N_CTA);   // (128, 8)
    int pp = 0;

    // encoder: t=0 has h=0 -> x-only GEMM (no PDL: depends on embed/init)
    launch_step<1>(grid, false, 0, pp, nullptr, nullptr, nullptr);
    pp ^= 1;
    for (int t = 1; t < SEQ; t++) {
        launch_step<0>(grid, true, t, pp, nullptr, nullptr, nullptr);
        pp ^= 1;
    }
    // decoder: x injected in epilogue; out fused via atomics
    for (int t = 0; t < TLEN; t++) {
        const float* prev = (t == 0) ? (x + (size_t)(SEQ - 1) * BATCH * INP)
                                     : (out + (size_t)(t - 1) * BATCH * 2);
        launch_step<2>(grid, true, 0, pp, prev,
                       out + (size_t)t * BATCH * 2, W_out);
        pp ^= 1;
    }
}

// round 14
// speedup vs baseline: 1.1096x; 1.0137x over previous
#include <cuda_runtime.h>
#include <cuda_fp16.h>
#include <cstdint>

#define SEQ   20
#define BATCH 16384
#define INP   2
#define HID   256
#define EMB   64
#define TLEN  30
#define NG    1024          /* 4*HID */
#define KC    64
#define NCH   4             /* uniform: 4 h-chunks, x injected in epilogue */

#define M_CTA  128
#define N_CTA  128
#define NSTAGE 3
#define A_TILE 16384        /* 64 k-rows x 128 m-cols x 2B (row pitch 256B) */
#define B_TILE 16384        /* 128 n-rows x 64 k x 2B (row pitch 128B) */
#define STAGE_BYTES (A_TILE + B_TILE)         /* 32KB */
#define SMEM_DYN_TOTAL (NSTAGE * STAGE_BYTES) /* 96KB */

/* MODE: 0 = encoder (x via rank-2 epilogue, Wxe = W_ih_enc @ W_emb),
         2 = decoder (x via rank-2 epilogue + fused out-projection) */

// ---------------- device scratch (all state [feature][batch]) ----------------
__device__ __half g_W_enc[NG * 256];   // [n][256] = W_hh_enc packed
__device__ __half g_W_dec[NG * 256];   // [n][256] = W_hh_dec packed
__device__ float g_Wxe[NG * 2];        // encoder (W_ih @ W_emb) [n][2] fp32
__device__ float g_Wxd[NG * 2];        // decoder W_ih [n][2] fp32
__device__ float g_bias_enc[NG];       // perm(b_enc) + W_ih_enc @ b_emb
__device__ float g_bias_dec[NG];
__device__ __half g_H[2][HID * BATCH]; // [j][b] single fp16 plane
__device__ float g_c[HID * BATCH];     // [j][b]

// ---------------- helpers ----------------
__device__ __forceinline__ uint32_t smem_to_u32(const void* p) {
    uint32_t a;
    asm("{ .reg .u64 t; cvta.to.shared.u64 t, %1; cvt.u32.u64 %0, t; }"
        : "=r"(a) : "l"(p));
    return a;
}
#define SWZ(o) ((o) ^ (((o) >> 3) & 0x70))
#define SWZA(kr, c16) ((kr) * 256 + (((c16) ^ ((kr) & 7)) << 4))

#define CP_ASYNC16(s, g) \
    asm volatile("cp.async.cg.shared.global [%0], [%1], 16;" \
                 :: "r"((uint32_t)(s)), "l"(g) : "memory")
#define CP_COMMIT() asm volatile("cp.async.commit_group;" ::: "memory")
template <int N>
__device__ __forceinline__ void cp_wait() {
    asm volatile("cp.async.wait_group %0;" :: "n"(N) : "memory");
}

#define PDL_WAIT()    asm volatile("griddepcontrol.wait;" ::: "memory")
#define PDL_TRIGGER() asm volatile("griddepcontrol.launch_dependents;" ::: "memory")

__device__ __forceinline__ void ldm_x4(uint32_t* r, uint32_t a) {
    asm volatile("ldmatrix.sync.aligned.m8n8.x4.shared.b16 {%0,%1,%2,%3}, [%4];"
                 : "=r"(r[0]), "=r"(r[1]), "=r"(r[2]), "=r"(r[3]) : "r"(a));
}
__device__ __forceinline__ void ldm_x4_trans(uint32_t* r, uint32_t a) {
    asm volatile("ldmatrix.sync.aligned.m8n8.x4.trans.shared.b16 {%0,%1,%2,%3}, [%4];"
                 : "=r"(r[0]), "=r"(r[1]), "=r"(r[2]), "=r"(r[3]) : "r"(a));
}
__device__ __forceinline__ void mma_f16(float* c, const uint32_t* a,
                                        uint32_t b0, uint32_t b1) {
    asm volatile(
        "mma.sync.aligned.m16n8k16.row.col.f32.f16.f16.f32 "
        "{%0,%1,%2,%3}, {%4,%5,%6,%7}, {%8,%9}, {%0,%1,%2,%3};"
        : "+f"(c[0]), "+f"(c[1]), "+f"(c[2]), "+f"(c[3])
        : "r"(a[0]), "r"(a[1]), "r"(a[2]), "r"(a[3]), "r"(b0), "r"(b1));
}

__device__ __forceinline__ float fsigmoid(float x) { return 1.0f / (1.0f + __expf(-x)); }
__device__ __forceinline__ float ftanh(float x) {
    float y;
    asm("tanh.approx.f32 %0, %1;" : "=f"(y) : "f"(x));
    return y;
}

// ---------------- prep kernels ----------------
__global__ void pack_enc_kernel(const float* __restrict__ W_ih,
                                const float* __restrict__ W_hh,
                                const float* __restrict__ b,
                                const float* __restrict__ W_emb,
                                const float* __restrict__ b_emb) {
    int idx = blockIdx.x * blockDim.x + threadIdx.x;
    if (idx < NG * 256) {
        int n = idx >> 8, kk = idx & 255;
        int j = n >> 2, g = n & 3;
        g_W_enc[idx] = __float2half_rn(W_hh[(g * HID + j) * HID + kk]);
    }
    if (idx < NG) {
        int j = idx >> 2, g = idx & 3;
        int row = g * HID + j;
        // Wxe = W_ih @ W_emb ; bias += W_ih @ b_emb  (all fp32, exact fold)
        float w0 = 0.0f, w1 = 0.0f, bb = 0.0f;
        for (int e = 0; e < EMB; e++) {
            float wie = W_ih[row * EMB + e];
            w0 = fmaf(wie, W_emb[e * 2 + 0], w0);
            w1 = fmaf(wie, W_emb[e * 2 + 1], w1);
            bb = fmaf(wie, b_emb[e], bb);
        }
        g_Wxe[idx * 2 + 0] = w0;
        g_Wxe[idx * 2 + 1] = w1;
        g_bias_enc[idx] = b[row] + bb;
    }
}

__global__ void pack_dec_kernel(const float* __restrict__ W_ih,
                                const float* __restrict__ W_hh,
                                const float* __restrict__ b) {
    int idx = blockIdx.x * blockDim.x + threadIdx.x;
    if (idx < NG * 256) {
        int n = idx >> 8, kk = idx & 255;
        int j = n >> 2, g = n & 3;
        g_W_dec[idx] = __float2half_rn(W_hh[(g * HID + j) * HID + kk]);
    }
    if (idx < NG) {
        int j = idx >> 2, g = idx & 3;
        g_bias_dec[idx] = b[g * HID + j];
    }
    if (idx < NG * 2) {
        int n = idx >> 1, k = idx & 1;
        int j = n >> 2, g = n & 3;
        g_Wxd[idx] = W_ih[(g * HID + j) * INP + k];
    }
}

// init_all: FUSED encoder step 0 (h0=c0=0 -> state s=1 from x[0] alone)
//           + out-buffer bias init.  Writes h1 into g_H[1].
__global__ void init_all_kernel(const float* __restrict__ x,
                                const float* __restrict__ b_out,
                                float* __restrict__ out) {
    int idx = blockIdx.x * blockDim.x + threadIdx.x;
    if (idx < HID * BATCH) {
        int b = idx & (BATCH - 1);
        int j = idx >> 14;
        float x0 = x[b * 2 + 0];          // t = 0 slice of x_input
        float x1 = x[b * 2 + 1];
        int n = j * 4;
        float gi = fmaf(x0, g_Wxe[(n + 0) * 2], fmaf(x1, g_Wxe[(n + 0) * 2 + 1], g_bias_enc[n + 0]));
        float gf = fmaf(x0, g_Wxe[(n + 1) * 2], fmaf(x1, g_Wxe[(n + 1) * 2 + 1], g_bias_enc[n + 1]));
        float gg = fmaf(x0, g_Wxe[(n + 2) * 2], fmaf(x1, g_Wxe[(n + 2) * 2 + 1], g_bias_enc[n + 2]));
        float go = fmaf(x0, g_Wxe[(n + 3) * 2], fmaf(x1, g_Wxe[(n + 3) * 2 + 1], g_bias_enc[n + 3]));
        (void)gf;  // c0 = 0 -> forget path contributes nothing
        float cn = fsigmoid(gi) * ftanh(gg);
        g_c[idx] = cn;
        g_H[1][idx] = __float2half_rn(fsigmoid(go) * ftanh(cn));
    }
    if (idx < TLEN * BATCH * 2) out[idx] = b_out[idx & 1];
}

// ---------------- fused HMMA LSTM step ----------------
// CTA 128(M batch)x128(N gates), 256 thr, 8 warps (2m x 4n), warp 64x32.
// K = 256 (4 chunks of h); x injected as exact fp32 rank-2 update in epilogue.
template <int MODE>
__global__ void __launch_bounds__(256, 2)
lstm_step_kernel(int ppi,
                 const float* __restrict__ prev,   // [b][2] fp32 (x[t] or out[t-1])
                 float* __restrict__ outp,         // MODE 2: out[t] [b][2]
                 const float* __restrict__ Wout) { // MODE 2: [2][256]
    extern __shared__ __align__(1024) char smem_raw[];
    const uint32_t sb = smem_to_u32(smem_raw);
    const int tid  = threadIdx.x;
    const int warp = tid >> 5, lane = tid & 31;
    const int wm = warp >> 2, wn = warp & 3;
    const int m0 = blockIdx.x * M_CTA, n0 = blockIdx.y * N_CTA;

    const __half* __restrict__ Wt  = (MODE == 2) ? g_W_dec : g_W_enc;
    const float* __restrict__ bias = (MODE == 2) ? g_bias_dec : g_bias_enc;
    const float* __restrict__ Wx   = (MODE == 2) ? g_Wxd : g_Wxe;
    const __half* __restrict__ hh  = g_H[ppi];
    __half* __restrict__ hho       = g_H[ppi ^ 1];

    auto load_W = [&](int ck, int st) {
        const uint32_t sW = sb + st * STAGE_BYTES + A_TILE;
        const int rw = tid >> 1;
        const __half* gw = Wt + (size_t)(n0 + rw) * 256 + ck * KC;
#pragma unroll
        for (int i = 0; i < 4; i++) {
            const int seg = (tid & 1) * 4 + i;
            CP_ASYNC16(sW + SWZ(rw * 128 + seg * 16), gw + seg * 8);
        }
    };
    auto load_A = [&](int ck, int st) {
        const uint32_t sA = sb + st * STAGE_BYTES;
        const int kr = tid >> 2;
        const __half* g = hh + (size_t)(ck * KC + kr) * BATCH + m0;
#pragma unroll
        for (int i = 0; i < 4; i++) {
            const int c16 = (tid & 3) * 4 + i;
            CP_ASYNC16(sA + SWZA(kr, c16), g + c16 * 8);
        }
    };

    float acc[4][4][4];
#pragma unroll
    for (int a = 0; a < 4; a++)
#pragma unroll
        for (int b = 0; b < 4; b++)
#pragma unroll
            for (int c = 0; c < 4; c++) acc[a][b][c] = 0.0f;

    // ---- prologue: weights pre-wait; h tiles after producer grid signals ----
    load_W(0, 0); load_W(1, 1);
    PDL_WAIT();
    load_A(0, 0); CP_COMMIT();
    load_A(1, 1); CP_COMMIT();

    for (int ck = 0; ck < NCH; ck++) {
        const int st = ck % NSTAGE;
        cp_wait<1>();
        __syncthreads();
        if (ck + 2 < NCH) {
            const int st2 = (ck + 2) % NSTAGE;
            load_W(ck + 2, st2);
            load_A(ck + 2, st2);
        }
        CP_COMMIT();
        if (ck == NCH - 1) PDL_TRIGGER();   // all loads issued: release successor

        const uint32_t sA = sb + st * STAGE_BYTES;
        const uint32_t sW = sA + A_TILE;
#pragma unroll
        for (int k16 = 0; k16 < 4; k16++) {
            uint32_t afr[4][4];
            const int kr = k16 * 16 + (lane & 7) + ((lane & 16) >> 1);
#pragma unroll
            for (int mt = 0; mt < 4; mt++) {
                const int mc = wm * 64 + mt * 16 + (lane & 8);
                ldm_x4_trans(afr[mt], sA + SWZA(kr, mc >> 3));
            }
            uint32_t bfr[2][4];
#pragma unroll
            for (int p = 0; p < 2; p++) {
                const int row  = wn * 32 + p * 16 + (lane & 7) + ((lane & 16) >> 1);
                const int kcol = k16 * 16 + ((lane & 8) ? 8 : 0);
                ldm_x4(bfr[p], sW + SWZ(row * 128 + kcol * 2));
            }
#pragma unroll
            for (int mt = 0; mt < 4; mt++)
#pragma unroll
                for (int nt = 0; nt < 4; nt++)
                    mma_f16(acc[mt][nt], afr[mt],
                            bfr[nt >> 1][(nt & 1) * 2],
                            bfr[nt >> 1][(nt & 1) * 2 + 1]);
        }
    }

    // ---- epilogue: rank-2 x injection + cell update (+ MODE2 out-projection) --
    const int odd = lane & 1;
    const int q   = (lane & 2) >> 1;
    float s0m[4] = {0, 0, 0, 0}, s1m[4] = {0, 0, 0, 0};
    float xv0[4], xv1[4];
#pragma unroll
    for (int mt = 0; mt < 4; mt++) {
        const int mrow = m0 + wm * 64 + mt * 16 + (lane >> 2) + 8 * odd;
        xv0[mt] = prev[mrow * 2 + 0];
        xv1[mt] = prev[mrow * 2 + 1];
    }
#pragma unroll
    for (int nt = 0; nt < 4; nt++) {
        const int nb = n0 + wn * 32 + nt * 8 + q * 4;
        const float4 bv = *(const float4*)&bias[nb];
        const int j = nb >> 2;
        float wx0[4], wx1[4], w_o0 = 0.0f, w_o1 = 0.0f;
#pragma unroll
        for (int r = 0; r < 4; r++) {
            wx0[r] = Wx[(nb + r) * 2 + 0];
            wx1[r] = Wx[(nb + r) * 2 + 1];
        }
        if (MODE == 2) {
            w_o0 = Wout[j];
            w_o1 = Wout[HID + j];
        }
#pragma unroll
        for (int mt = 0; mt < 4; mt++) {
            float o0 = __shfl_xor_sync(0xffffffffu, acc[mt][nt][0], 1);
            float o1 = __shfl_xor_sync(0xffffffffu, acc[mt][nt][1], 1);
            float o2 = __shfl_xor_sync(0xffffffffu, acc[mt][nt][2], 1);
            float o3 = __shfl_xor_sync(0xffffffffu, acc[mt][nt][3], 1);
            float gi, gf, gg, go;
            if (!odd) { gi = acc[mt][nt][0]; gf = acc[mt][nt][1]; gg = o0; go = o1; }
            else      { gi = o2; gf = o3; gg = acc[mt][nt][2]; go = acc[mt][nt][3]; }
            const int mrow = m0 + wm * 64 + mt * 16 + (lane >> 2) + 8 * odd;
            gi = fmaf(xv0[mt], wx0[0], fmaf(xv1[mt], wx1[0], gi)) + bv.x;
            gf = fmaf(xv0[mt], wx0[1], fmaf(xv1[mt], wx1[1], gf)) + bv.y;
            gg = fmaf(xv0[mt], wx0[2], fmaf(xv1[mt], wx1[2], gg)) + bv.z;
            go = fmaf(xv0[mt], wx0[3], fmaf(xv1[mt], wx1[3], go)) + bv.w;
            const size_t sidx = (size_t)j * BATCH + mrow;
            float cold = g_c[sidx];
            float cn = fsigmoid(gf) * cold + fsigmoid(gi) * ftanh(gg);
            g_c[sidx] = cn;
            float hn = fsigmoid(go) * ftanh(cn);
            hho[sidx] = __float2half_rn(hn);
            if (MODE == 2) {
                s0m[mt] = fmaf(hn, w_o0, s0m[mt]);
                s1m[mt] = fmaf(hn, w_o1, s1m[mt]);
            }
        }
    }

    // ---- MODE 2: reduce out partials and accumulate to out[t] ----
    if (MODE == 2) {
        float* sOut = (float*)smem_raw;   // 128 rows x 2
        __syncthreads();                  // all GEMM smem reads done
        sOut[tid] = 0.0f;
        __syncthreads();
#pragma unroll
        for (int mt = 0; mt < 4; mt++) {
            s0m[mt] += __shfl_xor_sync(0xffffffffu, s0m[mt], 2);
            s1m[mt] += __shfl_xor_sync(0xffffffffu, s1m[mt], 2);
        }
        if (!(lane & 2)) {
#pragma unroll
            for (int mt = 0; mt < 4; mt++) {
                const int r = wm * 64 + mt * 16 + (lane >> 2) + 8 * odd;
                atomicAdd(&sOut[r * 2 + 0], s0m[mt]);
                atomicAdd(&sOut[r * 2 + 1], s1m[mt]);
            }
        }
        __syncthreads();
        atomicAdd(&outp[(size_t)(m0 + (tid >> 1)) * 2 + (tid & 1)], sOut[tid]);
    }
}

// ---------------- host-side PDL launch helper ----------------
template <int MODE>
static void launch_step(dim3 grid, int pp,
                        const float* prev, float* outp, const float* Wout) {
    cudaLaunchConfig_t cfg = {};
    cfg.gridDim = grid;
    cfg.blockDim = dim3(256, 1, 1);
    cfg.dynamicSmemBytes = SMEM_DYN_TOTAL;
    cfg.stream = 0;
    cudaLaunchAttribute attr[1];
    attr[0].id = cudaLaunchAttributeProgrammaticStreamSerialization;
    attr[0].val.programmaticStreamSerializationAllowed = 1;
    cfg.attrs = attr;
    cfg.numAttrs = 1;
    cudaLaunchKernelEx(&cfg, lstm_step_kernel<MODE>, pp, prev, outp, Wout);
}

// ---------------- launch ----------------
extern "C" void kernel_launch(void* const* d_in, const int* in_sizes, int n_in,
                              void* d_out, int out_size) {
    const float* x        = (const float*)d_in[0];
    const float* W_emb    = (const float*)d_in[1];
    const float* b_emb    = (const float*)d_in[2];
    const float* W_ih_enc = (const float*)d_in[3];
    const float* W_hh_enc = (const float*)d_in[4];
    const float* b_enc    = (const float*)d_in[5];
    const float* W_ih_dec = (const float*)d_in[6];
    const float* W_hh_dec = (const float*)d_in[7];
    const float* b_dec    = (const float*)d_in[8];
    const float* W_out    = (const float*)d_in[9];
    const float* b_out    = (const float*)d_in[10];
    float* out = (float*)d_out;

    cudaFuncSetAttribute(lstm_step_kernel<0>,
                         cudaFuncAttributeMaxDynamicSharedMemorySize, SMEM_DYN_TOTAL);
    cudaFuncSetAttribute(lstm_step_kernel<2>,
                         cudaFuncAttributeMaxDynamicSharedMemorySize, SMEM_DYN_TOTAL);

    pack_enc_kernel<<<(NG * 256 + 255) / 256, 256>>>(W_ih_enc, W_hh_enc, b_enc,
                                                     W_emb, b_emb);
    pack_dec_kernel<<<(NG * 256 + 255) / 256, 256>>>(W_ih_dec, W_hh_dec, b_dec);
    // fused encoder step 0 (writes state s=1 into g_H[1]) + out bias init
    init_all_kernel<<<(HID * BATCH + 255) / 256, 256>>>(x, b_out, out);

    dim3 grid(BATCH / M_CTA, NG / N_CTA);   // (128, 8)
    int pp = 1;                              // state s=1 lives in g_H[1]

    // encoder steps t = 1..19 (x[t] injected in epilogue, exact fp32)
    for (int t = 1; t < SEQ; t++) {
        launch_step<0>(grid, pp, x + (size_t)t * BATCH * INP, nullptr, nullptr);
        pp ^= 1;
    }
    // decoder steps (x = previous output, out-projection fused)
    for (int t = 0; t < TLEN; t++) {
        const float* prev = (t == 0) ? (x + (size_t)(SEQ - 1) * BATCH * INP)
                                     : (out + (size_t)(t - 1) * BATCH * 2);
        launch_step<2>(grid, pp, prev, out + (size_t)t * BATCH * 2, W_out);
        pp ^= 1;
    }
}

// round 15
// speedup vs baseline: 1.1277x; 1.0163x over previous
#include <cuda_runtime.h>
#include <cuda_fp16.h>
#include <cstdint>

#define SEQ   20
#define BATCH 16384
#define INP   2
#define HID   256
#define EMB   64
#define TLEN  30
#define NG    1024          /* 4*HID */
#define KC    64
#define NCH   4             /* uniform: 4 h-chunks, x injected in epilogue */

#define M_CTA  128
#define N_CTA  128
#define NSTAGE 3
#define A_TILE 16384        /* 64 k-rows x 128 m-cols x 2B (row pitch 256B) */
#define B_TILE 16384        /* 128 n-rows x 64 k x 2B (row pitch 128B) */
#define STAGE_BYTES (A_TILE + B_TILE)         /* 32KB */
#define SMEM_C_OFF  (NSTAGE * STAGE_BYTES)    /* 96KB: c tile [32 j][128 m] f32 */
#define SMEM_DYN_TOTAL (SMEM_C_OFF + 16384)   /* 112KB */

/* MODE: 0 = encoder (x via rank-2 epilogue, Wxe = W_ih_enc @ W_emb),
         2 = decoder (x via rank-2 epilogue + fused out-projection) */

// ---------------- device scratch (all state [feature][batch]) ----------------
__device__ __half g_W_enc[NG * 256];   // [n][256] = W_hh_enc packed
__device__ __half g_W_dec[NG * 256];   // [n][256] = W_hh_dec packed
__device__ float g_Wxe[NG * 2];        // encoder (W_ih @ W_emb) [n][2] fp32
__device__ float g_Wxd[NG * 2];        // decoder W_ih [n][2] fp32
__device__ float g_bias_enc[NG];       // perm(b_enc) + W_ih_enc @ b_emb
__device__ float g_bias_dec[NG];
__device__ __half g_H[2][HID * BATCH]; // [j][b] single fp16 plane
__device__ float g_c[HID * BATCH];     // [j][b]

// ---------------- helpers ----------------
__device__ __forceinline__ uint32_t smem_to_u32(const void* p) {
    uint32_t a;
    asm("{ .reg .u64 t; cvta.to.shared.u64 t, %1; cvt.u32.u64 %0, t; }"
        : "=r"(a) : "l"(p));
    return a;
}
#define SWZ(o) ((o) ^ (((o) >> 3) & 0x70))
#define SWZA(kr, c16) ((kr) * 256 + (((c16) ^ ((kr) & 7)) << 4))

#define CP_ASYNC16(s, g) \
    asm volatile("cp.async.cg.shared.global [%0], [%1], 16;" \
                 :: "r"((uint32_t)(s)), "l"(g) : "memory")
#define CP_COMMIT() asm volatile("cp.async.commit_group;" ::: "memory")
template <int N>
__device__ __forceinline__ void cp_wait() {
    asm volatile("cp.async.wait_group %0;" :: "n"(N) : "memory");
}

#define PDL_WAIT()    asm volatile("griddepcontrol.wait;" ::: "memory")
#define PDL_TRIGGER() asm volatile("griddepcontrol.launch_dependents;" ::: "memory")

__device__ __forceinline__ void ldm_x4(uint32_t* r, uint32_t a) {
    asm volatile("ldmatrix.sync.aligned.m8n8.x4.shared.b16 {%0,%1,%2,%3}, [%4];"
                 : "=r"(r[0]), "=r"(r[1]), "=r"(r[2]), "=r"(r[3]) : "r"(a));
}
__device__ __forceinline__ void ldm_x4_trans(uint32_t* r, uint32_t a) {
    asm volatile("ldmatrix.sync.aligned.m8n8.x4.trans.shared.b16 {%0,%1,%2,%3}, [%4];"
                 : "=r"(r[0]), "=r"(r[1]), "=r"(r[2]), "=r"(r[3]) : "r"(a));
}
__device__ __forceinline__ void mma_f16(float* c, const uint32_t* a,
                                        uint32_t b0, uint32_t b1) {
    asm volatile(
        "mma.sync.aligned.m16n8k16.row.col.f32.f16.f16.f32 "
        "{%0,%1,%2,%3}, {%4,%5,%6,%7}, {%8,%9}, {%0,%1,%2,%3};"
        : "+f"(c[0]), "+f"(c[1]), "+f"(c[2]), "+f"(c[3])
        : "r"(a[0]), "r"(a[1]), "r"(a[2]), "r"(a[3]), "r"(b0), "r"(b1));
}

__device__ __forceinline__ float fsigmoid(float x) { return 1.0f / (1.0f + __expf(-x)); }
__device__ __forceinline__ float ftanh(float x) {
    float y;
    asm("tanh.approx.f32 %0, %1;" : "=f"(y) : "f"(x));
    return y;
}

// ---------------- prep kernels ----------------
__global__ void pack_enc_kernel(const float* __restrict__ W_ih,
                                const float* __restrict__ W_hh,
                                const float* __restrict__ b,
                                const float* __restrict__ W_emb,
                                const float* __restrict__ b_emb) {
    int idx = blockIdx.x * blockDim.x + threadIdx.x;
    if (idx < NG * 256) {
        int n = idx >> 8, kk = idx & 255;
        int j = n >> 2, g = n & 3;
        g_W_enc[idx] = __float2half_rn(W_hh[(g * HID + j) * HID + kk]);
    }
    if (idx < NG) {
        int j = idx >> 2, g = idx & 3;
        int row = g * HID + j;
        float w0 = 0.0f, w1 = 0.0f, bb = 0.0f;
        for (int e = 0; e < EMB; e++) {
            float wie = W_ih[row * EMB + e];
            w0 = fmaf(wie, W_emb[e * 2 + 0], w0);
            w1 = fmaf(wie, W_emb[e * 2 + 1], w1);
            bb = fmaf(wie, b_emb[e], bb);
        }
        g_Wxe[idx * 2 + 0] = w0;
        g_Wxe[idx * 2 + 1] = w1;
        g_bias_enc[idx] = b[row] + bb;
    }
}

__global__ void pack_dec_kernel(const float* __restrict__ W_ih,
                                const float* __restrict__ W_hh,
                                const float* __restrict__ b) {
    int idx = blockIdx.x * blockDim.x + threadIdx.x;
    if (idx < NG * 256) {
        int n = idx >> 8, kk = idx & 255;
        int j = n >> 2, g = n & 3;
        g_W_dec[idx] = __float2half_rn(W_hh[(g * HID + j) * HID + kk]);
    }
    if (idx < NG) {
        int j = idx >> 2, g = idx & 3;
        g_bias_dec[idx] = b[g * HID + j];
    }
    if (idx < NG * 2) {
        int n = idx >> 1, k = idx & 1;
        int j = n >> 2, g = n & 3;
        g_Wxd[idx] = W_ih[(g * HID + j) * INP + k];
    }
}

// init_all: FUSED encoder step 0 (h0=c0=0) + out bias init. Writes h1 to g_H[1].
__global__ void init_all_kernel(const float* __restrict__ x,
                                const float* __restrict__ b_out,
                                float* __restrict__ out) {
    int idx = blockIdx.x * blockDim.x + threadIdx.x;
    if (idx < HID * BATCH) {
        int b = idx & (BATCH - 1);
        int j = idx >> 14;
        float x0 = x[b * 2 + 0];
        float x1 = x[b * 2 + 1];
        int n = j * 4;
        float gi = fmaf(x0, g_Wxe[(n + 0) * 2], fmaf(x1, g_Wxe[(n + 0) * 2 + 1], g_bias_enc[n + 0]));
        float gg = fmaf(x0, g_Wxe[(n + 2) * 2], fmaf(x1, g_Wxe[(n + 2) * 2 + 1], g_bias_enc[n + 2]));
        float go = fmaf(x0, g_Wxe[(n + 3) * 2], fmaf(x1, g_Wxe[(n + 3) * 2 + 1], g_bias_enc[n + 3]));
        float cn = fsigmoid(gi) * ftanh(gg);
        g_c[idx] = cn;
        g_H[1][idx] = __float2half_rn(fsigmoid(go) * ftanh(cn));
    }
    if (idx < TLEN * BATCH * 2) out[idx] = b_out[idx & 1];
}

// ---------------- fused HMMA LSTM step ----------------
// CTA 128(M batch)x128(N gates), 256 thr, 8 warps (2m x 4n), warp 64x32.
// K = 256 (4 chunks of h); x injected as exact fp32 rank-2 update in epilogue.
// c staged through smem (cp.async with the prologue).
template <int MODE>
__global__ void __launch_bounds__(256, 2)
lstm_step_kernel(int ppi,
                 const float* __restrict__ prev,   // [b][2] fp32 (x[t] or out[t-1])
                 float* __restrict__ outp,         // MODE 2: out[t] [b][2]
                 const float* __restrict__ Wout) { // MODE 2: [2][256]
    extern __shared__ __align__(1024) char smem_raw[];
    const uint32_t sb = smem_to_u32(smem_raw);
    const int tid  = threadIdx.x;
    const int warp = tid >> 5, lane = tid & 31;
    const int wm = warp >> 2, wn = warp & 3;
    const int m0 = blockIdx.x * M_CTA, n0 = blockIdx.y * N_CTA;

    const __half* __restrict__ Wt  = (MODE == 2) ? g_W_dec : g_W_enc;
    const float* __restrict__ bias = (MODE == 2) ? g_bias_dec : g_bias_enc;
    const float* __restrict__ Wx   = (MODE == 2) ? g_Wxd : g_Wxe;
    const __half* __restrict__ hh  = g_H[ppi];
    __half* __restrict__ hho       = g_H[ppi ^ 1];

    auto load_W = [&](int ck, int st) {
        const uint32_t sW = sb + st * STAGE_BYTES + A_TILE;
        const int rw = tid >> 1;
        const __half* gw = Wt + (size_t)(n0 + rw) * 256 + ck * KC;
#pragma unroll
        for (int i = 0; i < 4; i++) {
            const int seg = (tid & 1) * 4 + i;
            CP_ASYNC16(sW + SWZ(rw * 128 + seg * 16), gw + seg * 8);
        }
    };
    auto load_A = [&](int ck, int st) {
        const uint32_t sA = sb + st * STAGE_BYTES;
        const int kr = tid >> 2;
        const __half* g = hh + (size_t)(ck * KC + kr) * BATCH + m0;
#pragma unroll
        for (int i = 0; i < 4; i++) {
            const int c16 = (tid & 3) * 4 + i;
            CP_ASYNC16(sA + SWZA(kr, c16), g + c16 * 8);
        }
    };
    auto load_C = [&]() {
        const uint32_t sC = sb + SMEM_C_OFF;
        const int jj = tid >> 3;                       // 0..31 local j
        const float* g = g_c + (size_t)((n0 >> 2) + jj) * BATCH + m0;
#pragma unroll
        for (int i = 0; i < 4; i++) {
            const int seg = (tid & 7) * 4 + i;         // 32 x 16B per row
            CP_ASYNC16(sC + jj * 512 + seg * 16, g + seg * 4);
        }
    };

    float acc[4][4][4];
#pragma unroll
    for (int a = 0; a < 4; a++)
#pragma unroll
        for (int b = 0; b < 4; b++)
#pragma unroll
            for (int c = 0; c < 4; c++) acc[a][b][c] = 0.0f;

    // ---- prologue: weights pre-wait; h/c tiles after predecessor completes ----
    load_W(0, 0); load_W(1, 1);
    PDL_WAIT();
    load_A(0, 0); CP_COMMIT();
    load_A(1, 1); load_C(); CP_COMMIT();
    PDL_TRIGGER();   // all correctness gating is in the successor's PDL_WAIT

    for (int ck = 0; ck < NCH; ck++) {
        const int st = ck % NSTAGE;
        cp_wait<1>();
        __syncthreads();
        if (ck + 2 < NCH) {
            const int st2 = (ck + 2) % NSTAGE;
            load_W(ck + 2, st2);
            load_A(ck + 2, st2);
        }
        CP_COMMIT();

        const uint32_t sA = sb + st * STAGE_BYTES;
        const uint32_t sW = sA + A_TILE;
#pragma unroll
        for (int k16 = 0; k16 < 4; k16++) {
            uint32_t afr[4][4];
            const int kr = k16 * 16 + (lane & 7) + ((lane & 16) >> 1);
#pragma unroll
            for (int mt = 0; mt < 4; mt++) {
                const int mc = wm * 64 + mt * 16 + (lane & 8);
                ldm_x4_trans(afr[mt], sA + SWZA(kr, mc >> 3));
            }
            uint32_t bfr[2][4];
#pragma unroll
            for (int p = 0; p < 2; p++) {
                const int row  = wn * 32 + p * 16 + (lane & 7) + ((lane & 16) >> 1);
                const int kcol = k16 * 16 + ((lane & 8) ? 8 : 0);
                ldm_x4(bfr[p], sW + SWZ(row * 128 + kcol * 2));
            }
#pragma unroll
            for (int mt = 0; mt < 4; mt++)
#pragma unroll
                for (int nt = 0; nt < 4; nt++)
                    mma_f16(acc[mt][nt], afr[mt],
                            bfr[nt >> 1][(nt & 1) * 2],
                            bfr[nt >> 1][(nt & 1) * 2 + 1]);
        }
    }

    // ---- epilogue: rank-2 x injection + cell update (+ MODE2 out-projection) --
    const float* sCf = (const float*)(smem_raw + SMEM_C_OFF);
    const int odd = lane & 1;
    const int q   = (lane & 2) >> 1;
    float s0m[4] = {0, 0, 0, 0}, s1m[4] = {0, 0, 0, 0};
    float xv0[4], xv1[4];
#pragma unroll
    for (int mt = 0; mt < 4; mt++) {
        const int mrow = m0 + wm * 64 + mt * 16 + (lane >> 2) + 8 * odd;
        xv0[mt] = prev[mrow * 2 + 0];
        xv1[mt] = prev[mrow * 2 + 1];
    }
#pragma unroll
    for (int nt = 0; nt < 4; nt++) {
        const int nb = n0 + wn * 32 + nt * 8 + q * 4;
        const float4 bv = *(const float4*)&bias[nb];
        const int j  = nb >> 2;
        const int jl = (wn * 32 + nt * 8 + q * 4) >> 2;   // local j in [0,32)
        float wx0[4], wx1[4], w_o0 = 0.0f, w_o1 = 0.0f;
#pragma unroll
        for (int r = 0; r < 4; r++) {
            wx0[r] = Wx[(nb + r) * 2 + 0];
            wx1[r] = Wx[(nb + r) * 2 + 1];
        }
        if (MODE == 2) {
            w_o0 = Wout[j];
            w_o1 = Wout[HID + j];
        }
#pragma unroll
        for (int mt = 0; mt < 4; mt++) {
            float o0 = __shfl_xor_sync(0xffffffffu, acc[mt][nt][0], 1);
            float o1 = __shfl_xor_sync(0xffffffffu, acc[mt][nt][1], 1);
            float o2 = __shfl_xor_sync(0xffffffffu, acc[mt][nt][2], 1);
            float o3 = __shfl_xor_sync(0xffffffffu, acc[mt][nt][3], 1);
            float gi, gf, gg, go;
            if (!odd) { gi = acc[mt][nt][0]; gf = acc[mt][nt][1]; gg = o0; go = o1; }
            else      { gi = o2; gf = o3; gg = acc[mt][nt][2]; go = acc[mt][nt][3]; }
            const int ml = wm * 64 + mt * 16 + (lane >> 2) + 8 * odd;  // local m
            const int mrow = m0 + ml;
            gi = fmaf(xv0[mt], wx0[0], fmaf(xv1[mt], wx1[0], gi)) + bv.x;
            gf = fmaf(xv0[mt], wx0[1], fmaf(xv1[mt], wx1[1], gf)) + bv.y;
            gg = fmaf(xv0[mt], wx0[2], fmaf(xv1[mt], wx1[2], gg)) + bv.z;
            go = fmaf(xv0[mt], wx0[3], fmaf(xv1[mt], wx1[3], go)) + bv.w;
            const size_t sidx = (size_t)j * BATCH + mrow;
            float cold = sCf[jl * 128 + ml];
            float cn = fsigmoid(gf) * cold + fsigmoid(gi) * ftanh(gg);
            g_c[sidx] = cn;
            float hn = fsigmoid(go) * ftanh(cn);
            hho[sidx] = __float2half_rn(hn);
            if (MODE == 2) {
                s0m[mt] = fmaf(hn, w_o0, s0m[mt]);
                s1m[mt] = fmaf(hn, w_o1, s1m[mt]);
            }
        }
    }

    // ---- MODE 2: reduce out partials and accumulate to out[t] ----
    if (MODE == 2) {
        float* sOut = (float*)smem_raw;   // 128 rows x 2 (stage-0 area)
        __syncthreads();                  // all GEMM smem reads done
        sOut[tid] = 0.0f;
        __syncthreads();
#pragma unroll
        for (int mt = 0; mt < 4; mt++) {
            s0m[mt] += __shfl_xor_sync(0xffffffffu, s0m[mt], 2);
            s1m[mt] += __shfl_xor_sync(0xffffffffu, s1m[mt], 2);
        }
        if (!(lane & 2)) {
#pragma unroll
            for (int mt = 0; mt < 4; mt++) {
                const int r = wm * 64 + mt * 16 + (lane >> 2) + 8 * odd;
                atomicAdd(&sOut[r * 2 + 0], s0m[mt]);
                atomicAdd(&sOut[r * 2 + 1], s1m[mt]);
            }
        }
        __syncthreads();
        atomicAdd(&outp[(size_t)(m0 + (tid >> 1)) * 2 + (tid & 1)], sOut[tid]);
    }
}

// ---------------- host-side PDL launch helper ----------------
template <int MODE>
static void launch_step(dim3 grid, int pp,
                        const float* prev, float* outp, const float* Wout) {
    cudaLaunchConfig_t cfg = {};
    cfg.gridDim = grid;
    cfg.blockDim = dim3(256, 1, 1);
    cfg.dynamicSmemBytes = SMEM_DYN_TOTAL;
    cfg.stream = 0;
    cudaLaunchAttribute attr[1];
    attr[0].id = cudaLaunchAttributeProgrammaticStreamSerialization;
    attr[0].val.programmaticStreamSerializationAllowed = 1;
    cfg.attrs = attr;
    cfg.numAttrs = 1;
    cudaLaunchKernelEx(&cfg, lstm_step_kernel<MODE>, pp, prev, outp, Wout);
}

// ---------------- launch ----------------
extern "C" void kernel_launch(void* const* d_in, const int* in_sizes, int n_in,
                              void* d_out, int out_size) {
    const float* x        = (const float*)d_in[0];
    const float* W_emb    = (const float*)d_in[1];
    const float* b_emb    = (const float*)d_in[2];
    const float* W_ih_enc = (const float*)d_in[3];
    const float* W_hh_enc = (const float*)d_in[4];
    const float* b_enc    = (const float*)d_in[5];
    const float* W_ih_dec = (const float*)d_in[6];
    const float* W_hh_dec = (const float*)d_in[7];
    const float* b_dec    = (const float*)d_in[8];
    const float* W_out    = (const float*)d_in[9];
    const float* b_out    = (const float*)d_in[10];
    float* out = (float*)d_out;

    cudaFuncSetAttribute(lstm_step_kernel<0>,
                         cudaFuncAttributeMaxDynamicSharedMemorySize, SMEM_DYN_TOTAL);
    cudaFuncSetAttribute(lstm_step_kernel<2>,
                         cudaFuncAttributeMaxDynamicSharedMemorySize, SMEM_DYN_TOTAL);

    pack_enc_kernel<<<(NG * 256 + 255) / 256, 256>>>(W_ih_enc, W_hh_enc, b_enc,
                                                     W_emb, b_emb);
    pack_dec_kernel<<<(NG * 256 + 255) / 256, 256>>>(W_ih_dec, W_hh_dec, b_dec);
    // fused encoder step 0 (writes state s=1 into g_H[1]) + out bias init
    init_all_kernel<<<(HID * BATCH + 255) / 256, 256>>>(x, b_out, out);

    dim3 grid(BATCH / M_CTA, NG / N_CTA);   // (128, 8)
    int pp = 1;                              // state s=1 lives in g_H[1]

    // encoder steps t = 1..19 (x[t] injected in epilogue, exact fp32)
    for (int t = 1; t < SEQ; t++) {
        launch_step<0>(grid, pp, x + (size_t)t * BATCH * INP, nullptr, nullptr);
        pp ^= 1;
    }
    // decoder steps (x = previous output, out-projection fused)
    for (int t = 0; t < TLEN; t++) {
        const float* prev = (t == 0) ? (x + (size_t)(SEQ - 1) * BATCH * INP)
                                     : (out + (size_t)(t - 1) * BATCH * 2);
        launch_step<2>(grid, pp, prev, out + (size_t)t * BATCH * 2, W_out);
        pp ^= 1;
    }
}